// round 1
// baseline (speedup 1.0000x reference)
#include <cuda_runtime.h>
#include <math.h>

#define BB 64
#define HH 512
#define EE 512
#define SS 2048
#define VV 32000
#define NSPLIT 32
#define SPLIT_S (SS / NSPLIT)

// ---------------- scratch (device globals, no allocation) ----------------
__device__ float g_x[BB * EE];              // relu(emb gather)
__device__ float g_gi[BB * 3 * HH];         // input gates
__device__ float g_gh[BB * 3 * HH];         // hidden gates
__device__ float g_A[BB * 2 * HH];          // [h_new | context] per batch
__device__ float g_u[BB * HH];              // u = h_new @ W_attn
__device__ float g_pctx[(size_t)NSPLIT * BB * HH]; // split context partials
__device__ float g_pml[NSPLIT * BB * 2];    // split (m, l)
__device__ float g_mlse[BB * 2];            // per-row (max, log-sum-exp)

// ---------------- K0: embedding gather + ReLU ----------------
__global__ void k_embed(const int* __restrict__ idx, const float* __restrict__ emb) {
    int b = blockIdx.x;
    int t = threadIdx.x;                    // 128 threads, float4 each
    int row = idx[b];
    const float4* src = (const float4*)(emb + (size_t)row * EE);
    float4* dst = (float4*)(g_x + b * EE);
    float4 v = src[t];
    v.x = fmaxf(v.x, 0.f); v.y = fmaxf(v.y, 0.f);
    v.z = fmaxf(v.z, 0.f); v.w = fmaxf(v.w, 0.f);
    dst[t] = v;
}

// ---------------- generic tiled GEMM: C[m,n] = sum_k A[m,k]*W[n,k] + bias[n]
// M = 64 fixed. BN = 64, BK = 32, 256 threads, 4x4 micro-tile.
__global__ void k_gemm_bt(const float* __restrict__ A, const float* __restrict__ W,
                          const float* __restrict__ bias, float* __restrict__ C,
                          int N, int K) {
    __shared__ float As[32][65];   // [k][m] padded
    __shared__ float Bs[32][65];   // [k][n] padded
    const int tid = threadIdx.x;
    const int tx = tid & 15, ty = tid >> 4;
    const int n0 = blockIdx.x * 64;

    float acc[4][4];
#pragma unroll
    for (int i = 0; i < 4; i++)
#pragma unroll
        for (int j = 0; j < 4; j++) acc[i][j] = 0.f;

    for (int k0 = 0; k0 < K; k0 += 32) {
#pragma unroll
        for (int i = tid; i < 64 * 32; i += 256) {
            int k = i & 31, m = i >> 5;
            As[k][m] = A[(size_t)m * K + k0 + k];
        }
#pragma unroll
        for (int i = tid; i < 64 * 32; i += 256) {
            int k = i & 31, n = i >> 5;
            Bs[k][n] = W[(size_t)(n0 + n) * K + k0 + k];
        }
        __syncthreads();
#pragma unroll
        for (int kk = 0; kk < 32; kk++) {
            float a[4], bv[4];
#pragma unroll
            for (int i = 0; i < 4; i++) a[i] = As[kk][ty * 4 + i];
#pragma unroll
            for (int j = 0; j < 4; j++) bv[j] = Bs[kk][tx * 4 + j];
#pragma unroll
            for (int i = 0; i < 4; i++)
#pragma unroll
                for (int j = 0; j < 4; j++) acc[i][j] += a[i] * bv[j];
        }
        __syncthreads();
    }
#pragma unroll
    for (int i = 0; i < 4; i++) {
        int m = ty * 4 + i;
#pragma unroll
        for (int j = 0; j < 4; j++) {
            int n = n0 + tx * 4 + j;
            C[(size_t)m * N + n] = acc[i][j] + bias[n];
        }
    }
}

// ---------------- K2: GRU gate combine -> h_new (into g_A[:,0:512] and d_out tail)
__global__ void k_gates(const float* __restrict__ h0, float* __restrict__ out_hidden) {
    int b = blockIdx.x, t = threadIdx.x;
    for (int h = t; h < HH; h += 256) {
        float gir = g_gi[b * 1536 + h],        ghr = g_gh[b * 1536 + h];
        float giz = g_gi[b * 1536 + 512 + h],  ghz = g_gh[b * 1536 + 512 + h];
        float gin = g_gi[b * 1536 + 1024 + h], ghn = g_gh[b * 1536 + 1024 + h];
        float r = 1.f / (1.f + __expf(-(gir + ghr)));
        float z = 1.f / (1.f + __expf(-(giz + ghz)));
        float n = tanhf(gin + r * ghn);
        float hv = (1.f - z) * n + z * h0[b * HH + h];
        g_A[b * 1024 + h] = hv;
        out_hidden[b * HH + h] = hv;
    }
}

// ---------------- K3: u[b,:] = h_new[b,:] @ W_attn  (64 blocks) ----------------
__global__ void k_u(const float* __restrict__ Wa) {
    int b = blockIdx.x, t = threadIdx.x;    // 256 threads, 2 cols each
    __shared__ float sh[HH];
    sh[t] = g_A[b * 1024 + t];
    sh[t + 256] = g_A[b * 1024 + t + 256];
    __syncthreads();
    float a0 = 0.f, a1 = 0.f;
    const float2* W2 = (const float2*)Wa;
#pragma unroll 8
    for (int h = 0; h < HH; h++) {
        float2 w = W2[(size_t)h * (HH / 2) + t];
        float hv = sh[h];
        a0 += hv * w.x;
        a1 += hv * w.y;
    }
    g_u[b * HH + 2 * t] = a0;
    g_u[b * HH + 2 * t + 1] = a1;
}

// ---------------- K4: online-softmax attention, split over S ----------------
__global__ void k_attn(const float* __restrict__ enc) {
    const int b = blockIdx.y;
    const int sp = blockIdx.x;
    const int t = threadIdx.x;              // 256 threads, float2 of the 512-dim row
    __shared__ float su[HH];
    __shared__ float red[8];
    __shared__ float s_alpha;
    su[t] = g_u[b * HH + t];
    su[t + 256] = g_u[b * HH + t + 256];
    __syncthreads();

    const float ux = su[2 * t], uy = su[2 * t + 1];
    float2 acc = make_float2(0.f, 0.f);
    float m = -INFINITY, l = 0.f;
    const int s0 = sp * SPLIT_S;

    // prefetch first row
    const float2* row0 = (const float2*)(enc + ((size_t)s0 * BB + b) * HH);
    float2 v = row0[t];

    for (int i = 0; i < SPLIT_S; i++) {
        float2 vn = make_float2(0.f, 0.f);
        if (i + 1 < SPLIT_S) {
            const float2* rn = (const float2*)(enc + ((size_t)(s0 + i + 1) * BB + b) * HH);
            vn = rn[t];                      // overlaps the barriers below
        }
        // block-reduce dot(enc_row, u)
        float p = v.x * ux + v.y * uy;
#pragma unroll
        for (int o = 16; o; o >>= 1) p += __shfl_xor_sync(0xffffffffu, p, o);
        if ((t & 31) == 0) red[t >> 5] = p;
        __syncthreads();
        if (t < 8) {
            float q = red[t];
#pragma unroll
            for (int o = 4; o; o >>= 1) q += __shfl_xor_sync(0xffu, q, o);
            if (t == 0) s_alpha = q;
        }
        __syncthreads();
        float alpha = s_alpha;
        float nm = fmaxf(m, alpha);
        float sc = __expf(m - nm);           // exp(-inf)=0 on first iter
        float w = __expf(alpha - nm);
        l = l * sc + w;
        acc.x = acc.x * sc + w * v.x;
        acc.y = acc.y * sc + w * v.y;
        m = nm;
        v = vn;
        __syncthreads();                     // protect red/s_alpha reuse
    }
    float2* pc = (float2*)(g_pctx + ((size_t)sp * BB + b) * HH);
    pc[t] = acc;
    if (t == 0) {
        g_pml[(sp * BB + b) * 2] = m;
        g_pml[(sp * BB + b) * 2 + 1] = l;
    }
}

// ---------------- K4b: combine splits -> context into g_A[:,512:1024] ----------------
__global__ void k_comb() {
    int b = blockIdx.x, t = threadIdx.x;     // 256 threads
    __shared__ float sm[NSPLIT], sl[NSPLIT];
    if (t < NSPLIT) {
        sm[t] = g_pml[(t * BB + b) * 2];
        sl[t] = g_pml[(t * BB + b) * 2 + 1];
    }
    __syncthreads();
    float M = -INFINITY;
#pragma unroll
    for (int i = 0; i < NSPLIT; i++) M = fmaxf(M, sm[i]);
    float L = 0.f;
#pragma unroll
    for (int i = 0; i < NSPLIT; i++) L += sl[i] * __expf(sm[i] - M);
    float inv = 1.f / L;
    float o0 = 0.f, o1 = 0.f;
#pragma unroll
    for (int i = 0; i < NSPLIT; i++) {
        float w = __expf(sm[i] - M);
        float2 p = ((const float2*)(g_pctx + ((size_t)i * BB + b) * HH))[t];
        o0 += w * p.x;
        o1 += w * p.y;
    }
    g_A[b * 1024 + 512 + 2 * t] = o0 * inv;
    g_A[b * 1024 + 512 + 2 * t + 1] = o1 * inv;
}

// ---------------- K5b: per-row max + log-sum-exp over V ----------------
__global__ void k_lse(const float* __restrict__ logits) {
    int b = blockIdx.x, t = threadIdx.x;     // 256 threads
    const float* row = logits + (size_t)b * VV;
    __shared__ float red[8];
    __shared__ float sM, sL;

    float mx = -INFINITY;
    for (int v = t; v < VV; v += 256) mx = fmaxf(mx, row[v]);
#pragma unroll
    for (int o = 16; o; o >>= 1) mx = fmaxf(mx, __shfl_xor_sync(0xffffffffu, mx, o));
    if ((t & 31) == 0) red[t >> 5] = mx;
    __syncthreads();
    if (t < 8) {
        float q = red[t];
#pragma unroll
        for (int o = 4; o; o >>= 1) q = fmaxf(q, __shfl_xor_sync(0xffu, q, o));
        if (t == 0) sM = q;
    }
    __syncthreads();
    float M = sM;

    float sum = 0.f;
    for (int v = t; v < VV; v += 256) sum += __expf(row[v] - M);
#pragma unroll
    for (int o = 16; o; o >>= 1) sum += __shfl_xor_sync(0xffffffffu, sum, o);
    if ((t & 31) == 0) red[t >> 5] = sum;
    __syncthreads();
    if (t < 8) {
        float q = red[t];
#pragma unroll
        for (int o = 4; o; o >>= 1) q += __shfl_xor_sync(0xffu, q, o);
        if (t == 0) sL = q;
    }
    __syncthreads();
    if (t == 0) {
        g_mlse[2 * b] = M;
        g_mlse[2 * b + 1] = logf(sL);
    }
}

// ---------------- K5c: log_softmax fixup ----------------
__global__ void k_fix(float* __restrict__ out) {
    int b = blockIdx.y;
    int v = blockIdx.x * 256 + threadIdx.x;
    out[(size_t)b * VV + v] -= g_mlse[2 * b] + g_mlse[2 * b + 1];
}

// ---------------- launch ----------------
extern "C" void kernel_launch(void* const* d_in, const int* in_sizes, int n_in,
                              void* d_out, int out_size) {
    const int*   dec_inputs = (const int*)d_in[0];
    const float* enc        = (const float*)d_in[1];
    const float* h0         = (const float*)d_in[2];
    const float* emb        = (const float*)d_in[3];
    const float* W_ih       = (const float*)d_in[4];
    const float* W_hh       = (const float*)d_in[5];
    const float* b_ih       = (const float*)d_in[6];
    const float* b_hh       = (const float*)d_in[7];
    const float* W_attn     = (const float*)d_in[8];
    const float* b_attn     = (const float*)d_in[9];   // cancels in softmax; unused
    const float* W_cls      = (const float*)d_in[10];
    const float* b_cls      = (const float*)d_in[11];
    (void)b_attn; (void)in_sizes; (void)n_in; (void)out_size;

    float* out        = (float*)d_out;                 // [64, 32000] log-softmax
    float* out_hidden = (float*)d_out + (size_t)BB * VV; // [1, 64, 512]

    float *px, *pgi, *pgh, *pA;
    cudaGetSymbolAddress((void**)&px,  g_x);
    cudaGetSymbolAddress((void**)&pgi, g_gi);
    cudaGetSymbolAddress((void**)&pgh, g_gh);
    cudaGetSymbolAddress((void**)&pA,  g_A);

    // 1. embedding + relu
    k_embed<<<BB, 128>>>(dec_inputs, emb);
    // 2. GRU gate GEMMs
    k_gemm_bt<<<1536 / 64, 256>>>(px, W_ih, b_ih, pgi, 1536, 512);
    k_gemm_bt<<<1536 / 64, 256>>>(h0, W_hh, b_hh, pgh, 1536, 512);
    // 3. gate combine -> h_new (also writes dec_hidden output)
    k_gates<<<BB, 256>>>(h0, out_hidden);
    // 4. u = h_new @ W_attn
    k_u<<<BB, 256>>>(W_attn);
    // 5. online-softmax attention over S (split)
    k_attn<<<dim3(NSPLIT, BB), 256>>>(enc);
    k_comb<<<BB, 256>>>();
    // 6. classifier logits straight into d_out
    k_gemm_bt<<<VV / 64, 256>>>(pA, W_cls, b_cls, out, VV, 1024);
    // 7. log-softmax
    k_lse<<<BB, 256>>>(out);
    k_fix<<<dim3(VV / 256, BB), 256>>>(out);
}

// round 2
// speedup vs baseline: 1.0553x; 1.0553x over previous
#include <cuda_runtime.h>
#include <math.h>

#define BB 64
#define HH 512
#define EE 512
#define SS 2048
#define VV 32000
#define NSPLIT 32
#define SPLIT_S (SS / NSPLIT)

// ---------------- scratch (device globals, no allocation) ----------------
__device__ float g_x[BB * EE];
__device__ float g_gi[BB * 3 * HH];
__device__ float g_gh[BB * 3 * HH];
__device__ float g_A[BB * 2 * HH];          // [h_new | context]
__device__ float g_u[BB * HH];
__device__ float g_pctx[(size_t)NSPLIT * BB * HH];
__device__ float g_pml[NSPLIT * BB * 2];
__device__ float g_mlse[BB * 2];

// ---------------- K0: embedding gather + ReLU ----------------
__global__ void k_embed(const int* __restrict__ idx, const float* __restrict__ emb) {
    int b = blockIdx.x;
    int t = threadIdx.x;
    int row = idx[b];
    const float4* src = (const float4*)(emb + (size_t)row * EE);
    float4* dst = (float4*)(g_x + b * EE);
    float4 v = src[t];
    v.x = fmaxf(v.x, 0.f); v.y = fmaxf(v.y, 0.f);
    v.z = fmaxf(v.z, 0.f); v.w = fmaxf(v.w, 0.f);
    dst[t] = v;
}

// ---------------- 64x128 tile GEMM core, 128 threads, 8x8 micro-tile ----
// C[m, n0+n] = sum_k A[m,k] * W[n0+n, k] + bias[n0+n],  M=64 fixed.
__device__ __forceinline__ void gemm_tile8(const float* __restrict__ A,
                                           const float* __restrict__ W,
                                           const float* __restrict__ bias,
                                           float* __restrict__ C,
                                           int N, int K, int n0) {
    __shared__ float As[16][68];    // [k][m], stride 68 floats (16B aligned)
    __shared__ float Bs[16][132];   // [k][n], stride 132 floats

    const int tid = threadIdx.x;
    const int mt = (tid >> 4) * 8;  // 0..56
    const int nt = (tid & 15) * 8;  // 0..120

    float acc[8][8];
#pragma unroll
    for (int i = 0; i < 8; i++)
#pragma unroll
        for (int j = 0; j < 8; j++) acc[i][j] = 0.f;

    for (int k0 = 0; k0 < K; k0 += 16) {
        // A tile: 64 rows x 16 k  = 256 float4
#pragma unroll
        for (int i = tid; i < 256; i += 128) {
            int m = i >> 2, kq = (i & 3) * 4;
            float4 v = *(const float4*)(A + (size_t)m * K + k0 + kq);
            As[kq + 0][m] = v.x; As[kq + 1][m] = v.y;
            As[kq + 2][m] = v.z; As[kq + 3][m] = v.w;
        }
        // W tile: 128 rows x 16 k = 512 float4
#pragma unroll
        for (int i = tid; i < 512; i += 128) {
            int n = i >> 2, kq = (i & 3) * 4;
            float4 v = *(const float4*)(W + (size_t)(n0 + n) * K + k0 + kq);
            Bs[kq + 0][n] = v.x; Bs[kq + 1][n] = v.y;
            Bs[kq + 2][n] = v.z; Bs[kq + 3][n] = v.w;
        }
        __syncthreads();
#pragma unroll
        for (int kk = 0; kk < 16; kk++) {
            float4 a0 = *(const float4*)&As[kk][mt];
            float4 a1 = *(const float4*)&As[kk][mt + 4];
            float4 b0 = *(const float4*)&Bs[kk][nt];
            float4 b1 = *(const float4*)&Bs[kk][nt + 4];
            float a[8] = {a0.x, a0.y, a0.z, a0.w, a1.x, a1.y, a1.z, a1.w};
            float bv[8] = {b0.x, b0.y, b0.z, b0.w, b1.x, b1.y, b1.z, b1.w};
#pragma unroll
            for (int i = 0; i < 8; i++)
#pragma unroll
                for (int j = 0; j < 8; j++) acc[i][j] += a[i] * bv[j];
        }
        __syncthreads();
    }

    float4 bi0 = *(const float4*)(bias + n0 + nt);
    float4 bi1 = *(const float4*)(bias + n0 + nt + 4);
#pragma unroll
    for (int i = 0; i < 8; i++) {
        int m = mt + i;
        float4 o0, o1;
        o0.x = acc[i][0] + bi0.x; o0.y = acc[i][1] + bi0.y;
        o0.z = acc[i][2] + bi0.z; o0.w = acc[i][3] + bi0.w;
        o1.x = acc[i][4] + bi1.x; o1.y = acc[i][5] + bi1.y;
        o1.z = acc[i][6] + bi1.z; o1.w = acc[i][7] + bi1.w;
        *(float4*)(C + (size_t)m * N + n0 + nt)     = o0;
        *(float4*)(C + (size_t)m * N + n0 + nt + 4) = o1;
    }
}

// Both GRU gate GEMMs in one launch (24 blocks).
__global__ void k_gru_gemms(const float* __restrict__ x, const float* __restrict__ h0,
                            const float* __restrict__ W_ih, const float* __restrict__ W_hh,
                            const float* __restrict__ b_ih, const float* __restrict__ b_hh,
                            float* __restrict__ gi, float* __restrict__ gh) {
    if (blockIdx.x < 12)
        gemm_tile8(x, W_ih, b_ih, gi, 3 * HH, EE, blockIdx.x * 128);
    else
        gemm_tile8(h0, W_hh, b_hh, gh, 3 * HH, HH, (blockIdx.x - 12) * 128);
}

// Classifier (250 blocks).
__global__ void k_cls(const float* __restrict__ A, const float* __restrict__ W,
                      const float* __restrict__ bias, float* __restrict__ C) {
    gemm_tile8(A, W, bias, C, VV, 2 * HH, blockIdx.x * 128);
}

// ---------------- K2: GRU gate combine ----------------
__global__ void k_gates(const float* __restrict__ h0, float* __restrict__ out_hidden) {
    int i = blockIdx.x * 256 + threadIdx.x;   // 0..32767
    int b = i >> 9, h = i & 511;
    float gir = g_gi[b * 1536 + h],        ghr = g_gh[b * 1536 + h];
    float giz = g_gi[b * 1536 + 512 + h],  ghz = g_gh[b * 1536 + 512 + h];
    float gin = g_gi[b * 1536 + 1024 + h], ghn = g_gh[b * 1536 + 1024 + h];
    float r = 1.f / (1.f + __expf(-(gir + ghr)));
    float z = 1.f / (1.f + __expf(-(giz + ghz)));
    float n = tanhf(gin + r * ghn);
    float hv = (1.f - z) * n + z * h0[b * HH + h];
    g_A[b * 1024 + h] = hv;
    out_hidden[b * HH + h] = hv;
}

// ---------------- K3: u[b,:] = h_new[b,:] @ W_attn ----------------
__global__ void k_u(const float* __restrict__ Wa) {
    int b = blockIdx.x, t = threadIdx.x;    // 256 threads, 2 cols each
    __shared__ float sh[HH];
    sh[t] = g_A[b * 1024 + t];
    sh[t + 256] = g_A[b * 1024 + t + 256];
    __syncthreads();
    float a0 = 0.f, a1 = 0.f;
    const float2* W2 = (const float2*)Wa;
#pragma unroll 8
    for (int h = 0; h < HH; h++) {
        float2 w = W2[(size_t)h * (HH / 2) + t];
        float hv = sh[h];
        a0 += hv * w.x;
        a1 += hv * w.y;
    }
    g_u[b * HH + 2 * t] = a0;
    g_u[b * HH + 2 * t + 1] = a1;
}

// ---------------- K4: attention, warp-per-row (no in-loop barriers) ------
__global__ void k_attn(const float* __restrict__ enc) {
    const int b = blockIdx.y;
    const int sp = blockIdx.x;
    const int t = threadIdx.x;              // 256 threads = 8 warps
    const int wid = t >> 5, lane = t & 31;
    __shared__ float su[HH];
    __shared__ float sctx[8][HH];
    __shared__ float sml[8][2];

    su[t] = g_u[b * HH + t];
    su[t + 256] = g_u[b * HH + t + 256];
    __syncthreads();

    float4 u4[4];
#pragma unroll
    for (int j = 0; j < 4; j++) u4[j] = ((const float4*)su)[lane + 32 * j];

    float m = -INFINITY, l = 0.f;
    float4 acc[4];
#pragma unroll
    for (int j = 0; j < 4; j++) acc[j] = make_float4(0.f, 0.f, 0.f, 0.f);

    const int s0 = sp * SPLIT_S;
    // prefetch first row for this warp
    float4 v[4];
    {
        const float4* row = (const float4*)(enc + ((size_t)(s0 + wid) * BB + b) * HH);
#pragma unroll
        for (int j = 0; j < 4; j++) v[j] = row[lane + 32 * j];
    }

    for (int i = wid; i < SPLIT_S; i += 8) {
        float4 vn[4];
        if (i + 8 < SPLIT_S) {
            const float4* rn = (const float4*)(enc + ((size_t)(s0 + i + 8) * BB + b) * HH);
#pragma unroll
            for (int j = 0; j < 4; j++) vn[j] = rn[lane + 32 * j];
        } else {
#pragma unroll
            for (int j = 0; j < 4; j++) vn[j] = make_float4(0.f, 0.f, 0.f, 0.f);
        }
        float p = 0.f;
#pragma unroll
        for (int j = 0; j < 4; j++)
            p += v[j].x * u4[j].x + v[j].y * u4[j].y + v[j].z * u4[j].z + v[j].w * u4[j].w;
#pragma unroll
        for (int o = 16; o; o >>= 1) p += __shfl_xor_sync(0xffffffffu, p, o);

        float nm = fmaxf(m, p);
        float sc = __expf(m - nm);
        float w = __expf(p - nm);
        l = l * sc + w;
#pragma unroll
        for (int j = 0; j < 4; j++) {
            acc[j].x = acc[j].x * sc + w * v[j].x;
            acc[j].y = acc[j].y * sc + w * v[j].y;
            acc[j].z = acc[j].z * sc + w * v[j].z;
            acc[j].w = acc[j].w * sc + w * v[j].w;
        }
        m = nm;
#pragma unroll
        for (int j = 0; j < 4; j++) v[j] = vn[j];
    }

    // cross-warp combine (one barrier total)
#pragma unroll
    for (int j = 0; j < 4; j++) ((float4*)sctx[wid])[lane + 32 * j] = acc[j];
    if (lane == 0) { sml[wid][0] = m; sml[wid][1] = l; }
    __syncthreads();

    float M = -INFINITY;
#pragma unroll
    for (int w = 0; w < 8; w++) M = fmaxf(M, sml[w][0]);
    float L = 0.f, c0 = 0.f, c1 = 0.f;
#pragma unroll
    for (int w = 0; w < 8; w++) {
        float e = __expf(sml[w][0] - M);
        L += e * sml[w][1];
        c0 += e * sctx[w][t];
        c1 += e * sctx[w][t + 256];
    }
    size_t base = ((size_t)sp * BB + b) * HH;
    g_pctx[base + t] = c0;
    g_pctx[base + t + 256] = c1;
    if (t == 0) {
        g_pml[(sp * BB + b) * 2] = M;
        g_pml[(sp * BB + b) * 2 + 1] = L;
    }
}

// ---------------- K4b: combine splits -> context ----------------
__global__ void k_comb() {
    int b = blockIdx.x, t = threadIdx.x;     // 256 threads
    __shared__ float sm[NSPLIT], sl[NSPLIT];
    if (t < NSPLIT) {
        sm[t] = g_pml[(t * BB + b) * 2];
        sl[t] = g_pml[(t * BB + b) * 2 + 1];
    }
    __syncthreads();
    float M = -INFINITY;
#pragma unroll
    for (int i = 0; i < NSPLIT; i++) M = fmaxf(M, sm[i]);
    float L = 0.f;
#pragma unroll
    for (int i = 0; i < NSPLIT; i++) L += sl[i] * __expf(sm[i] - M);
    float inv = 1.f / L;
    float o0 = 0.f, o1 = 0.f;
#pragma unroll
    for (int i = 0; i < NSPLIT; i++) {
        float w = __expf(sm[i] - M);
        size_t base = ((size_t)i * BB + b) * HH;
        o0 += w * g_pctx[base + t];
        o1 += w * g_pctx[base + t + 256];
    }
    g_A[b * 1024 + 512 + t] = o0 * inv;
    g_A[b * 1024 + 512 + t + 256] = o1 * inv;
}

// ---------------- K5b: per-row max + log-sum-exp over V ----------------
__global__ void k_lse(const float* __restrict__ logits) {
    int b = blockIdx.x, t = threadIdx.x;     // 512 threads
    const float* row = logits + (size_t)b * VV;
    __shared__ float red[16];
    __shared__ float sM, sL;

    float mx = -INFINITY;
    for (int v = t; v < VV; v += 512) mx = fmaxf(mx, row[v]);
#pragma unroll
    for (int o = 16; o; o >>= 1) mx = fmaxf(mx, __shfl_xor_sync(0xffffffffu, mx, o));
    if ((t & 31) == 0) red[t >> 5] = mx;
    __syncthreads();
    if (t < 16) {
        float q = red[t];
#pragma unroll
        for (int o = 8; o; o >>= 1) q = fmaxf(q, __shfl_xor_sync(0xffffu, q, o));
        if (t == 0) sM = q;
    }
    __syncthreads();
    float M = sM;

    float sum = 0.f;
    for (int v = t; v < VV; v += 512) sum += __expf(row[v] - M);
#pragma unroll
    for (int o = 16; o; o >>= 1) sum += __shfl_xor_sync(0xffffffffu, sum, o);
    if ((t & 31) == 0) red[t >> 5] = sum;
    __syncthreads();
    if (t < 16) {
        float q = red[t];
#pragma unroll
        for (int o = 8; o; o >>= 1) q += __shfl_xor_sync(0xffffu, q, o);
        if (t == 0) sL = q;
    }
    __syncthreads();
    if (t == 0) {
        g_mlse[2 * b] = M;
        g_mlse[2 * b + 1] = logf(sL);
    }
}

// ---------------- K5c: log_softmax fixup ----------------
__global__ void k_fix(float* __restrict__ out) {
    int b = blockIdx.y;
    int v = blockIdx.x * 256 + threadIdx.x;
    out[(size_t)b * VV + v] -= g_mlse[2 * b] + g_mlse[2 * b + 1];
}

// ---------------- launch ----------------
extern "C" void kernel_launch(void* const* d_in, const int* in_sizes, int n_in,
                              void* d_out, int out_size) {
    const int*   dec_inputs = (const int*)d_in[0];
    const float* enc        = (const float*)d_in[1];
    const float* h0         = (const float*)d_in[2];
    const float* emb        = (const float*)d_in[3];
    const float* W_ih       = (const float*)d_in[4];
    const float* W_hh       = (const float*)d_in[5];
    const float* b_ih       = (const float*)d_in[6];
    const float* b_hh       = (const float*)d_in[7];
    const float* W_attn     = (const float*)d_in[8];
    const float* b_attn     = (const float*)d_in[9];   // cancels in softmax
    const float* W_cls      = (const float*)d_in[10];
    const float* b_cls      = (const float*)d_in[11];
    (void)b_attn; (void)in_sizes; (void)n_in; (void)out_size;

    float* out        = (float*)d_out;
    float* out_hidden = (float*)d_out + (size_t)BB * VV;

    float *px, *pgi, *pgh, *pA;
    cudaGetSymbolAddress((void**)&px,  g_x);
    cudaGetSymbolAddress((void**)&pgi, g_gi);
    cudaGetSymbolAddress((void**)&pgh, g_gh);
    cudaGetSymbolAddress((void**)&pA,  g_A);

    k_embed<<<BB, 128>>>(dec_inputs, emb);
    k_gru_gemms<<<24, 128>>>(px, h0, W_ih, W_hh, b_ih, b_hh, pgi, pgh);
    k_gates<<<BB * HH / 256, 256>>>(h0, out_hidden);
    k_u<<<BB, 256>>>(W_attn);
    k_attn<<<dim3(NSPLIT, BB), 256>>>(enc);
    k_comb<<<BB, 256>>>();
    k_cls<<<VV / 128, 128>>>(pA, W_cls, b_cls, out);
    k_lse<<<BB, 512>>>(out);
    k_fix<<<dim3(VV / 256, BB), 256>>>(out);
}

// round 3
// speedup vs baseline: 2.0761x; 1.9672x over previous
#include <cuda_runtime.h>
#include <math.h>

#define BB 64
#define HH 512
#define EE 512
#define SS 2048
#define VV 32000
#define NSPLIT 32
#define SPLIT_S (SS / NSPLIT)

#define FMA_F32X2(d, a, b, c) \
    asm("fma.rn.f32x2 %0, %1, %2, %3;" : "=l"(d) : "l"(a), "l"(b), "l"(c))
#define PACK_BCAST(d, f) \
    asm("mov.b64 %0, {%1, %1};" : "=l"(d) : "r"(__float_as_uint(f)))

// ---------------- scratch ----------------
__device__ float g_x[BB * EE];
__device__ float g_gi[BB * 3 * HH];
__device__ float g_gh[BB * 3 * HH];
__device__ float g_A[BB * 2 * HH];          // [h_new | context]
__device__ float g_u[BB * HH];
__device__ float g_pctx[(size_t)NSPLIT * BB * HH];
__device__ float g_pml[NSPLIT * BB * 2];

// ---------------- K0: embedding gather + ReLU ----------------
__global__ void k_embed(const int* __restrict__ idx, const float* __restrict__ emb) {
    int b = blockIdx.x;
    int t = threadIdx.x;
    int row = idx[b];
    const float4* src = (const float4*)(emb + (size_t)row * EE);
    float4* dst = (float4*)(g_x + b * EE);
    float4 v = src[t];
    v.x = fmaxf(v.x, 0.f); v.y = fmaxf(v.y, 0.f);
    v.z = fmaxf(v.z, 0.f); v.w = fmaxf(v.w, 0.f);
    dst[t] = v;
}

// ---------------- GEMM core: 64M x 128N tile, 128 thr, 8x8 micro (f32x2) ----
// BT=true : C[m,n] = sum_k A[m,k]*W[n,k]  (W row-major over n)
// BT=false: C[m,n] = sum_k A[m,k]*W[k,n]  (W row-major over k)
template<bool BT, bool HASB, bool ATOM>
__device__ __forceinline__ void gemm8(const float* __restrict__ A, int lda,
                                      const float* __restrict__ W, int ldw,
                                      const float* __restrict__ bias,
                                      float* __restrict__ C, int ldc,
                                      int K, int n0) {
    __shared__ float As[2][16][68];
    __shared__ float Bs[2][16][132];
    const int tid = threadIdx.x;
    const int mt = (tid >> 4) * 8;
    const int nt = (tid & 15) * 8;

    unsigned long long acc2[8][4];
#pragma unroll
    for (int i = 0; i < 8; i++)
#pragma unroll
        for (int j = 0; j < 4; j++) acc2[i][j] = 0ull;

    float4 ra[2], rb[4];

    auto ldG = [&](int k0) {
#pragma unroll
        for (int r = 0; r < 2; r++) {
            int i = tid + r * 128;
            int m = i >> 2, kq = (i & 3) * 4;
            ra[r] = *(const float4*)(A + (size_t)m * lda + k0 + kq);
        }
#pragma unroll
        for (int r = 0; r < 4; r++) {
            int i = tid + r * 128;
            if (BT) {
                int n = i >> 2, kq = (i & 3) * 4;
                rb[r] = *(const float4*)(W + (size_t)(n0 + n) * ldw + k0 + kq);
            } else {
                int k = i >> 5, nq = (i & 31) * 4;
                rb[r] = *(const float4*)(W + (size_t)(k0 + k) * ldw + n0 + nq);
            }
        }
    };
    auto stS = [&](int buf) {
#pragma unroll
        for (int r = 0; r < 2; r++) {
            int i = tid + r * 128;
            int m = i >> 2, kq = (i & 3) * 4;
            As[buf][kq + 0][m] = ra[r].x; As[buf][kq + 1][m] = ra[r].y;
            As[buf][kq + 2][m] = ra[r].z; As[buf][kq + 3][m] = ra[r].w;
        }
#pragma unroll
        for (int r = 0; r < 4; r++) {
            int i = tid + r * 128;
            if (BT) {
                int n = i >> 2, kq = (i & 3) * 4;
                Bs[buf][kq + 0][n] = rb[r].x; Bs[buf][kq + 1][n] = rb[r].y;
                Bs[buf][kq + 2][n] = rb[r].z; Bs[buf][kq + 3][n] = rb[r].w;
            } else {
                int k = i >> 5, nq = (i & 31) * 4;
                *(float4*)&Bs[buf][k][nq] = rb[r];
            }
        }
    };

    ldG(0);
    stS(0);
    __syncthreads();
    const int ntile = K / 16;
    for (int t = 0; t < ntile; t++) {
        const int cur = t & 1;
        if (t + 1 < ntile) ldG((t + 1) * 16);
#pragma unroll
        for (int kk = 0; kk < 16; kk++) {
            float4 a0 = *(const float4*)&As[cur][kk][mt];
            float4 a1 = *(const float4*)&As[cur][kk][mt + 4];
            const unsigned long long* bp =
                (const unsigned long long*)&Bs[cur][kk][nt];
            unsigned long long pb0 = bp[0], pb1 = bp[1], pb2 = bp[2], pb3 = bp[3];
            float a[8] = {a0.x, a0.y, a0.z, a0.w, a1.x, a1.y, a1.z, a1.w};
#pragma unroll
            for (int i = 0; i < 8; i++) {
                unsigned long long pa;
                PACK_BCAST(pa, a[i]);
                FMA_F32X2(acc2[i][0], pa, pb0, acc2[i][0]);
                FMA_F32X2(acc2[i][1], pa, pb1, acc2[i][1]);
                FMA_F32X2(acc2[i][2], pa, pb2, acc2[i][2]);
                FMA_F32X2(acc2[i][3], pa, pb3, acc2[i][3]);
            }
        }
        if (t + 1 < ntile) stS(cur ^ 1);
        __syncthreads();
    }

    float bi[8] = {0, 0, 0, 0, 0, 0, 0, 0};
    if (HASB) {
        float4 b0 = *(const float4*)(bias + n0 + nt);
        float4 b1 = *(const float4*)(bias + n0 + nt + 4);
        bi[0] = b0.x; bi[1] = b0.y; bi[2] = b0.z; bi[3] = b0.w;
        bi[4] = b1.x; bi[5] = b1.y; bi[6] = b1.z; bi[7] = b1.w;
    }
#pragma unroll
    for (int i = 0; i < 8; i++) {
        float o[8];
#pragma unroll
        for (int jp = 0; jp < 4; jp++) {
            float2 f = *reinterpret_cast<float2*>(&acc2[i][jp]);
            o[2 * jp] = f.x + bi[2 * jp];
            o[2 * jp + 1] = f.y + bi[2 * jp + 1];
        }
        size_t base = (size_t)(mt + i) * ldc + n0 + nt;
        if (ATOM) {
#pragma unroll
            for (int j = 0; j < 8; j++) atomicAdd(&C[base + j], o[j]);
        } else {
            float4 v0 = make_float4(o[0], o[1], o[2], o[3]);
            float4 v1 = make_float4(o[4], o[5], o[6], o[7]);
            *(float4*)(C + base) = v0;
            *(float4*)(C + base + 4) = v1;
        }
    }
}

// GRU gate GEMMs (24 blocks)
__global__ void k_gru(const float* __restrict__ x, const float* __restrict__ h0,
                      const float* __restrict__ W_ih, const float* __restrict__ W_hh,
                      const float* __restrict__ b_ih, const float* __restrict__ b_hh,
                      float* __restrict__ gi, float* __restrict__ gh) {
    if (blockIdx.x < 12)
        gemm8<true, true, false>(x, EE, W_ih, EE, b_ih, gi, 3 * HH, EE, blockIdx.x * 128);
    else
        gemm8<true, true, false>(h0, HH, W_hh, HH, b_hh, gh, 3 * HH, HH, (blockIdx.x - 12) * 128);
}

// u = h_new @ W_attn : K-split GEMM into zeroed g_u (16 blocks)
__global__ void k_u_gemm(const float* __restrict__ Wa) {
    int n0 = (blockIdx.x & 3) * 128;
    int koff = (blockIdx.x >> 2) * 128;
    gemm8<false, false, true>(g_A + koff, 1024, Wa + (size_t)koff * HH, HH,
                              nullptr, g_u, HH, 128, n0);
}

// classifier (250 blocks)
__global__ void k_cls(const float* __restrict__ W, const float* __restrict__ bias,
                      float* __restrict__ C) {
    gemm8<true, true, false>(g_A, 1024, W, 2 * HH, bias, C, VV, 2 * HH, blockIdx.x * 128);
}

// ---------------- K2: GRU gate combine ----------------
__global__ void k_gates(const float* __restrict__ h0, float* __restrict__ out_hidden) {
    int i = blockIdx.x * 256 + threadIdx.x;
    int b = i >> 9, h = i & 511;
    float gir = g_gi[b * 1536 + h],        ghr = g_gh[b * 1536 + h];
    float giz = g_gi[b * 1536 + 512 + h],  ghz = g_gh[b * 1536 + 512 + h];
    float gin = g_gi[b * 1536 + 1024 + h], ghn = g_gh[b * 1536 + 1024 + h];
    float r = 1.f / (1.f + __expf(-(gir + ghr)));
    float z = 1.f / (1.f + __expf(-(giz + ghz)));
    float n = tanhf(gin + r * ghn);
    float hv = (1.f - z) * n + z * h0[b * HH + h];
    g_A[b * 1024 + h] = hv;
    out_hidden[b * HH + h] = hv;
}

// ---------------- K4: attention, warp-per-row ----------------
__global__ void k_attn(const float* __restrict__ enc) {
    const int b = blockIdx.y;
    const int sp = blockIdx.x;
    const int t = threadIdx.x;
    const int wid = t >> 5, lane = t & 31;
    __shared__ float su[HH];
    __shared__ float sctx[8][HH];
    __shared__ float sml[8][2];

    su[t] = g_u[b * HH + t];
    su[t + 256] = g_u[b * HH + t + 256];
    __syncthreads();

    float4 u4[4];
#pragma unroll
    for (int j = 0; j < 4; j++) u4[j] = ((const float4*)su)[lane + 32 * j];

    float m = -INFINITY, l = 0.f;
    float4 acc[4];
#pragma unroll
    for (int j = 0; j < 4; j++) acc[j] = make_float4(0.f, 0.f, 0.f, 0.f);

    const int s0 = sp * SPLIT_S;
    float4 v[4];
    {
        const float4* row = (const float4*)(enc + ((size_t)(s0 + wid) * BB + b) * HH);
#pragma unroll
        for (int j = 0; j < 4; j++) v[j] = row[lane + 32 * j];
    }

    for (int i = wid; i < SPLIT_S; i += 8) {
        float4 vn[4];
        if (i + 8 < SPLIT_S) {
            const float4* rn = (const float4*)(enc + ((size_t)(s0 + i + 8) * BB + b) * HH);
#pragma unroll
            for (int j = 0; j < 4; j++) vn[j] = rn[lane + 32 * j];
        } else {
#pragma unroll
            for (int j = 0; j < 4; j++) vn[j] = make_float4(0.f, 0.f, 0.f, 0.f);
        }
        float p = 0.f;
#pragma unroll
        for (int j = 0; j < 4; j++)
            p += v[j].x * u4[j].x + v[j].y * u4[j].y + v[j].z * u4[j].z + v[j].w * u4[j].w;
#pragma unroll
        for (int o = 16; o; o >>= 1) p += __shfl_xor_sync(0xffffffffu, p, o);

        float nm = fmaxf(m, p);
        float sc = __expf(m - nm);
        float w = __expf(p - nm);
        l = l * sc + w;
#pragma unroll
        for (int j = 0; j < 4; j++) {
            acc[j].x = acc[j].x * sc + w * v[j].x;
            acc[j].y = acc[j].y * sc + w * v[j].y;
            acc[j].z = acc[j].z * sc + w * v[j].z;
            acc[j].w = acc[j].w * sc + w * v[j].w;
        }
        m = nm;
#pragma unroll
        for (int j = 0; j < 4; j++) v[j] = vn[j];
    }

#pragma unroll
    for (int j = 0; j < 4; j++) ((float4*)sctx[wid])[lane + 32 * j] = acc[j];
    if (lane == 0) { sml[wid][0] = m; sml[wid][1] = l; }
    __syncthreads();

    float M = -INFINITY;
#pragma unroll
    for (int w = 0; w < 8; w++) M = fmaxf(M, sml[w][0]);
    float L = 0.f, c0 = 0.f, c1 = 0.f;
#pragma unroll
    for (int w = 0; w < 8; w++) {
        float e = __expf(sml[w][0] - M);
        L += e * sml[w][1];
        c0 += e * sctx[w][t];
        c1 += e * sctx[w][t + 256];
    }
    size_t base = ((size_t)sp * BB + b) * HH;
    g_pctx[base + t] = c0;
    g_pctx[base + t + 256] = c1;
    if (t == 0) {
        g_pml[(sp * BB + b) * 2] = M;
        g_pml[(sp * BB + b) * 2 + 1] = L;
    }
}

// ---------------- K4b: combine splits ----------------
__global__ void k_comb() {
    int b = blockIdx.x, t = threadIdx.x;
    __shared__ float sm[NSPLIT], sl[NSPLIT];
    if (t < NSPLIT) {
        sm[t] = g_pml[(t * BB + b) * 2];
        sl[t] = g_pml[(t * BB + b) * 2 + 1];
    }
    __syncthreads();
    float M = -INFINITY;
#pragma unroll
    for (int i = 0; i < NSPLIT; i++) M = fmaxf(M, sm[i]);
    float L = 0.f;
#pragma unroll
    for (int i = 0; i < NSPLIT; i++) L += sl[i] * __expf(sm[i] - M);
    float inv = 1.f / L;
    float o0 = 0.f, o1 = 0.f;
#pragma unroll
    for (int i = 0; i < NSPLIT; i++) {
        float w = __expf(sm[i] - M);
        size_t base = ((size_t)i * BB + b) * HH;
        o0 += w * g_pctx[base + t];
        o1 += w * g_pctx[base + t + 256];
    }
    g_A[b * 1024 + 512 + t] = o0 * inv;
    g_A[b * 1024 + 512 + t + 256] = o1 * inv;
}

// ---------------- fused log-softmax (max + lse + subtract) ----------------
__global__ void k_lsefix(float* __restrict__ out) {
    const int b = blockIdx.x, t = threadIdx.x;   // 1024 threads
    float4* row = (float4*)(out + (size_t)b * VV);
    __shared__ float red[32];
    __shared__ float sM, sL;
    const int lane = t & 31, wid = t >> 5;

    float mx = -INFINITY;
    for (int i = t; i < VV / 4; i += 1024) {
        float4 v = row[i];
        mx = fmaxf(mx, fmaxf(fmaxf(v.x, v.y), fmaxf(v.z, v.w)));
    }
#pragma unroll
    for (int o = 16; o; o >>= 1) mx = fmaxf(mx, __shfl_xor_sync(0xffffffffu, mx, o));
    if (lane == 0) red[wid] = mx;
    __syncthreads();
    if (t < 32) {
        float q = red[t];
#pragma unroll
        for (int o = 16; o; o >>= 1) q = fmaxf(q, __shfl_xor_sync(0xffffffffu, q, o));
        if (t == 0) sM = q;
    }
    __syncthreads();
    const float M = sM;

    float s = 0.f;
    for (int i = t; i < VV / 4; i += 1024) {
        float4 v = row[i];
        s += __expf(v.x - M) + __expf(v.y - M) + __expf(v.z - M) + __expf(v.w - M);
    }
#pragma unroll
    for (int o = 16; o; o >>= 1) s += __shfl_xor_sync(0xffffffffu, s, o);
    if (lane == 0) red[wid] = s;
    __syncthreads();
    if (t < 32) {
        float q = red[t];
#pragma unroll
        for (int o = 16; o; o >>= 1) q += __shfl_xor_sync(0xffffffffu, q, o);
        if (t == 0) sL = q;
    }
    __syncthreads();
    const float c = M + logf(sL);

    for (int i = t; i < VV / 4; i += 1024) {
        float4 v = row[i];
        v.x -= c; v.y -= c; v.z -= c; v.w -= c;
        row[i] = v;
    }
}

// ---------------- launch ----------------
extern "C" void kernel_launch(void* const* d_in, const int* in_sizes, int n_in,
                              void* d_out, int out_size) {
    const int*   dec_inputs = (const int*)d_in[0];
    const float* enc        = (const float*)d_in[1];
    const float* h0         = (const float*)d_in[2];
    const float* emb        = (const float*)d_in[3];
    const float* W_ih       = (const float*)d_in[4];
    const float* W_hh       = (const float*)d_in[5];
    const float* b_ih       = (const float*)d_in[6];
    const float* b_hh       = (const float*)d_in[7];
    const float* W_attn     = (const float*)d_in[8];
    const float* b_attn     = (const float*)d_in[9];   // cancels in softmax
    const float* W_cls      = (const float*)d_in[10];
    const float* b_cls      = (const float*)d_in[11];
    (void)b_attn; (void)in_sizes; (void)n_in; (void)out_size;

    float* out        = (float*)d_out;
    float* out_hidden = (float*)d_out + (size_t)BB * VV;

    float *px, *pgi, *pgh, *pu;
    cudaGetSymbolAddress((void**)&px,  g_x);
    cudaGetSymbolAddress((void**)&pgi, g_gi);
    cudaGetSymbolAddress((void**)&pgh, g_gh);
    cudaGetSymbolAddress((void**)&pu,  g_u);

    k_embed<<<BB, 128>>>(dec_inputs, emb);
    k_gru<<<24, 128>>>(px, h0, W_ih, W_hh, b_ih, b_hh, pgi, pgh);
    k_gates<<<BB * HH / 256, 256>>>(h0, out_hidden);
    cudaMemsetAsync(pu, 0, (size_t)BB * HH * sizeof(float));
    k_u_gemm<<<16, 128>>>(W_attn);
    k_attn<<<dim3(NSPLIT, BB), 256>>>(enc);
    k_comb<<<BB, 256>>>();
    k_cls<<<VV / 128, 128>>>(W_cls, b_cls, out);
    k_lsefix<<<BB, 1024>>>(out);
}